// round 1
// baseline (speedup 1.0000x reference)
#include <cuda_runtime.h>
#include <cuda_bf16.h>
#include <math.h>

// Problem constants
#define NB 16          // batch
#define LQ 300         // queries
#define CC 256         // channels
#define NH 8           // heads
#define HD 32          // head dim
#define NL 3           // levels
#define NP 4           // points
#define LV 8400        // total spatial positions
#define TPX 96         // H*L*P

// Scratch (device globals; no runtime allocation allowed)
__device__ float  g_v[NB * LV * CC];          // value @ W_val + b_val   (137.6 MB)
__device__ float4 g_samp[NB * LQ * TPX];      // (gx_px, gy_px, aw, _)   (7.4 MB)
__device__ float  g_mid[NB * LQ * CC];        // per-head aggregated     (4.9 MB)

__constant__ int c_start[NL] = {0, 6400, 8000};
__constant__ int c_w[NL]     = {80, 40, 20};
__constant__ int c_h[NL]     = {80, 40, 20};

// ---------------------------------------------------------------------------
// Kernel 1: C = A(MxK) @ B(KxN) + bias, row-major, all dims multiples of tile
// 128x128 block tile, BK=16, 256 threads, 8x8 per-thread tile.
// ---------------------------------------------------------------------------
__global__ __launch_bounds__(256) void sgemm128(
    const float* __restrict__ A, const float* __restrict__ B,
    const float* __restrict__ bias, float* __restrict__ C,
    int M, int N, int K)
{
    __shared__ float As[16][128];
    __shared__ float Bs[16][128];

    const int tid = threadIdx.x;
    const int tx = tid & 15;       // 0..15
    const int ty = tid >> 4;       // 0..15
    const int rowBase = blockIdx.y * 128;
    const int colBase = blockIdx.x * 128;

    float acc[8][8];
#pragma unroll
    for (int i = 0; i < 8; i++)
#pragma unroll
        for (int j = 0; j < 8; j++) acc[i][j] = 0.f;

    for (int k0 = 0; k0 < K; k0 += 16) {
        // Load A tile 128x16 (transposed into As[k][m])
#pragma unroll
        for (int i = 0; i < 2; i++) {
            int idx = tid + i * 256;       // 0..511
            int r   = idx >> 2;            // 0..127
            int c4  = (idx & 3) * 4;       // 0,4,8,12
            float4 v = *(const float4*)&A[(size_t)(rowBase + r) * K + k0 + c4];
            As[c4 + 0][r] = v.x;
            As[c4 + 1][r] = v.y;
            As[c4 + 2][r] = v.z;
            As[c4 + 3][r] = v.w;
        }
        // Load B tile 16x128
#pragma unroll
        for (int i = 0; i < 2; i++) {
            int idx = tid + i * 256;       // 0..511
            int r   = idx >> 5;            // 0..15
            int c4  = (idx & 31) * 4;      // 0..124
            *(float4*)&Bs[r][c4] =
                *(const float4*)&B[(size_t)(k0 + r) * N + colBase + c4];
        }
        __syncthreads();

#pragma unroll
        for (int kk = 0; kk < 16; kk++) {
            float a[8], b[8];
            *(float4*)(a)     = *(const float4*)&As[kk][ty * 8];
            *(float4*)(a + 4) = *(const float4*)&As[kk][ty * 8 + 4];
            *(float4*)(b)     = *(const float4*)&Bs[kk][tx * 8];
            *(float4*)(b + 4) = *(const float4*)&Bs[kk][tx * 8 + 4];
#pragma unroll
            for (int i = 0; i < 8; i++)
#pragma unroll
                for (int j = 0; j < 8; j++)
                    acc[i][j] += a[i] * b[j];
        }
        __syncthreads();
    }

    // Epilogue: add bias, store
#pragma unroll
    for (int i = 0; i < 8; i++) {
        int row = rowBase + ty * 8 + i;
#pragma unroll
        for (int j = 0; j < 8; j += 4) {
            int col = colBase + tx * 8 + j;
            float4 o;
            o.x = acc[i][j + 0] + bias[col + 0];
            o.y = acc[i][j + 1] + bias[col + 1];
            o.z = acc[i][j + 2] + bias[col + 2];
            o.w = acc[i][j + 3] + bias[col + 3];
            *(float4*)&C[(size_t)row * N + col] = o;
        }
    }
}

// ---------------------------------------------------------------------------
// Kernel 2: sampling params. 8 queries/block, 288 threads.
// off = q@W_off+b_off (192), attn = softmax_perhead(q@W_attn+b_attn) (96)
// -> g_samp[(fq)*96 + j] = (gx_pixel, gy_pixel, aw, 0)
// ---------------------------------------------------------------------------
__global__ __launch_bounds__(288) void params_kernel(
    const float* __restrict__ query, const float* __restrict__ refp,
    const float* __restrict__ Woff, const float* __restrict__ boff,
    const float* __restrict__ Wattn, const float* __restrict__ battn)
{
    __shared__ float qs[8][CC];
    __shared__ float off_s[8][192];
    __shared__ float attn_s[8][TPX];

    const int tid = threadIdx.x;
    const int qbase = blockIdx.x * 8;   // flat query row, contiguous over (n, q)

    // load 8 query rows
    for (int idx = tid; idx < 8 * CC; idx += 288) {
        int i = idx >> 8;
        int k = idx & 255;
        qs[i][k] = query[(size_t)(qbase + i) * CC + k];
    }
    __syncthreads();

    // GEMM: each thread handles one output column for all 8 queries
    {
        const int j = tid;  // 0..287
        float acc[8];
#pragma unroll
        for (int i = 0; i < 8; i++) acc[i] = 0.f;
        if (j < 192) {
            for (int k = 0; k < CC; k++) {
                float wv = Woff[k * 192 + j];
#pragma unroll
                for (int i = 0; i < 8; i++) acc[i] += qs[i][k] * wv;
            }
            float bb = boff[j];
#pragma unroll
            for (int i = 0; i < 8; i++) off_s[i][j] = acc[i] + bb;
        } else {
            int ja = j - 192;
            for (int k = 0; k < CC; k++) {
                float wv = Wattn[k * TPX + ja];
#pragma unroll
                for (int i = 0; i < 8; i++) acc[i] += qs[i][k] * wv;
            }
            float bb = battn[ja];
#pragma unroll
            for (int i = 0; i < 8; i++) attn_s[i][ja] = acc[i] + bb;
        }
    }
    __syncthreads();

    // softmax over the 12 (l,p) entries per head: 8 queries x 8 heads = 64
    if (tid < 64) {
        int i = tid >> 3;
        int h = tid & 7;
        float* a = &attn_s[i][h * 12];
        float m = a[0];
#pragma unroll
        for (int r = 1; r < 12; r++) m = fmaxf(m, a[r]);
        float s = 0.f;
        float e[12];
#pragma unroll
        for (int r = 0; r < 12; r++) { e[r] = __expf(a[r] - m); s += e[r]; }
        float inv = 1.f / s;
#pragma unroll
        for (int r = 0; r < 12; r++) a[r] = e[r] * inv;
    }
    __syncthreads();

    // sampling locations: 8 queries x 96 points = 768
    for (int idx = tid; idx < 8 * TPX; idx += 288) {
        int i = idx / TPX;
        int j = idx % TPX;          // j = h*12 + l*4 + p
        int r = j % 12;
        int l = r >> 2;
        int fq = qbase + i;

        const float* rp = &refp[((size_t)fq * NL + l) * 4];
        float cx = rp[0], cy = rp[1], rw = rp[2], rh = rp[3];
        float ox = off_s[i][j * 2 + 0];
        float oy = off_s[i][j * 2 + 1];
        // loc = c + off/P * wh * 0.5  -> off * 0.125 * wh
        float lx = cx + ox * 0.125f * rw;
        float ly = cy + oy * 0.125f * rh;
        float4 o;
        o.x = lx * (float)c_w[l] - 0.5f;   // gx pixel
        o.y = ly * (float)c_h[l] - 0.5f;   // gy pixel
        o.z = attn_s[i][j];
        o.w = 0.f;
        g_samp[(size_t)fq * TPX + j] = o;
    }
}

// ---------------------------------------------------------------------------
// Kernel 3: deformable sampling + aggregation. One warp per (n,q,h).
// 32 lanes = 32 head channels. 12 points x 4 bilinear corners.
// ---------------------------------------------------------------------------
__global__ __launch_bounds__(256) void sample_kernel()
{
    const int warpInBlock = threadIdx.x >> 5;
    const int lane = threadIdx.x & 31;
    const int wg = blockIdx.x * 8 + warpInBlock;   // 0 .. 38399
    const int h  = wg & 7;
    const int fq = wg >> 3;                        // flat (n*300+q)
    const int n  = fq / LQ;

    // Each of lanes 0..11 loads one sample descriptor
    float4 s = make_float4(0.f, 0.f, 0.f, 0.f);
    if (lane < 12) s = g_samp[(size_t)fq * TPX + h * 12 + lane];

    const float* vbase = &g_v[((size_t)n * LV) * CC + h * HD + lane];

    float acc = 0.f;
#pragma unroll
    for (int r = 0; r < 12; r++) {
        float gx = __shfl_sync(0xffffffffu, s.x, r);
        float gy = __shfl_sync(0xffffffffu, s.y, r);
        float aw = __shfl_sync(0xffffffffu, s.z, r);
        int l = r >> 2;
        int W = c_w[l], Hh = c_h[l], st = c_start[l];

        float x0f = floorf(gx), y0f = floorf(gy);
        float fx = gx - x0f, fy = gy - y0f;
        int ix = (int)x0f, iy = (int)y0f;

        bool vx0 = (ix >= 0) & (ix < W);
        bool vx1 = (ix + 1 >= 0) & (ix + 1 < W);
        bool vy0 = (iy >= 0) & (iy < Hh);
        bool vy1 = (iy + 1 >= 0) & (iy + 1 < Hh);

        const float* row0 = vbase + (size_t)(st + iy * W) * CC;
        const float* row1 = row0 + (size_t)W * CC;

        float v00 = (vx0 & vy0) ? row0[(size_t)ix * CC]       : 0.f;
        float v01 = (vx1 & vy0) ? row0[(size_t)(ix + 1) * CC] : 0.f;
        float v10 = (vx0 & vy1) ? row1[(size_t)ix * CC]       : 0.f;
        float v11 = (vx1 & vy1) ? row1[(size_t)(ix + 1) * CC] : 0.f;

        float bil = v00 * (1.f - fx) * (1.f - fy)
                  + v01 * fx * (1.f - fy)
                  + v10 * (1.f - fx) * fy
                  + v11 * fx * fy;
        acc += aw * bil;
    }
    g_mid[(size_t)fq * CC + h * HD + lane] = acc;
}

// ---------------------------------------------------------------------------
// Kernel 4: out = mid @ W_out + b_out.  8 queries/block, 256 threads.
// ---------------------------------------------------------------------------
__global__ __launch_bounds__(256) void out_kernel(
    const float* __restrict__ Wout, const float* __restrict__ bout,
    float* __restrict__ out)
{
    __shared__ float ms[8][CC];
    const int tid = threadIdx.x;
    const int qbase = blockIdx.x * 8;

    for (int idx = tid; idx < 8 * CC; idx += 256) {
        int i = idx >> 8;
        int k = idx & 255;
        ms[i][k] = g_mid[(size_t)(qbase + i) * CC + k];
    }
    __syncthreads();

    const int j = tid;
    float acc[8];
#pragma unroll
    for (int i = 0; i < 8; i++) acc[i] = 0.f;
    for (int k = 0; k < CC; k++) {
        float wv = Wout[k * CC + j];
#pragma unroll
        for (int i = 0; i < 8; i++) acc[i] += ms[i][k] * wv;
    }
    float bb = bout[j];
#pragma unroll
    for (int i = 0; i < 8; i++)
        out[(size_t)(qbase + i) * CC + j] = acc[i] + bb;
}

// ---------------------------------------------------------------------------
extern "C" void kernel_launch(void* const* d_in, const int* in_sizes, int n_in,
                              void* d_out, int out_size)
{
    const float* query = (const float*)d_in[0];
    const float* refp  = (const float*)d_in[1];
    const float* value = (const float*)d_in[2];
    const float* Woff  = (const float*)d_in[3];
    const float* boff  = (const float*)d_in[4];
    const float* Wattn = (const float*)d_in[5];
    const float* battn = (const float*)d_in[6];
    const float* Wval  = (const float*)d_in[7];
    const float* bval  = (const float*)d_in[8];
    const float* Wout  = (const float*)d_in[9];
    const float* bout  = (const float*)d_in[10];
    float* out = (float*)d_out;

    float* d_v;
    cudaGetSymbolAddress((void**)&d_v, g_v);

    // 1) v = value @ W_val + b_val  (M=NB*LV=134400, K=256, N=256)
    {
        dim3 grid(CC / 128, (NB * LV) / 128);
        sgemm128<<<grid, 256>>>(value, Wval, bval, d_v, NB * LV, CC, CC);
    }
    // 2) sampling params (off GEMM + attn GEMM + softmax + locations)
    params_kernel<<<(NB * LQ) / 8, 288>>>(query, refp, Woff, boff, Wattn, battn);
    // 3) deformable sampling/aggregation
    sample_kernel<<<(NB * LQ * NH) / 8, 256>>>();
    // 4) output projection
    out_kernel<<<(NB * LQ) / 8, 256>>>(Wout, bout, out);
}

// round 7
// speedup vs baseline: 1.4786x; 1.4786x over previous
#include <cuda_runtime.h>
#include <cuda_bf16.h>
#include <math.h>
#include <stdint.h>

// Problem constants
#define NB 16          // batch
#define LQ 300         // queries
#define CC 256         // channels
#define NH 8           // heads
#define HD 32          // head dim
#define NL 3           // levels
#define NP 4           // points
#define LV 8400        // total spatial positions
#define TPX 96         // H*L*P
#define NQ (NB * LQ)   // 4800 flat queries

// Scratch (device globals; no runtime allocation allowed)
__device__ float  g_v[NB * LV * CC];          // value @ W_val + b_val   (137.6 MB)
__device__ float  g_off[NQ * 192];            // offset GEMM out         (3.7 MB)
__device__ float  g_attn[NQ * TPX];           // attn GEMM out (pre-softmax)
__device__ float4 g_samp[NQ * TPX];           // (gx_px, gy_px, aw, _)   (7.4 MB)
__device__ float  g_mid[NQ * CC];             // per-head aggregated     (4.9 MB)

__constant__ int c_start[NL] = {0, 6400, 8000};
__constant__ int c_w[NL]     = {80, 40, 20};
__constant__ int c_h[NL]     = {80, 40, 20};

// ---------------------------------------------------------------------------
// TF32 tensor-core GEMM: C = A(MxK) @ B(KxN) + bias
// BM=128, BN=128, BK=32. 256 threads = 8 warps (2 M x 4 N), warp tile 64x32.
// mma.sync.aligned.m16n8k8.row.col.f32.tf32.tf32.f32
// K must be a multiple of 32; M, N arbitrary (guarded), N % 4 == 0.
// ---------------------------------------------------------------------------
__device__ __forceinline__ uint32_t f2tf32(float f) {
    uint32_t r;
    asm("cvt.rna.tf32.f32 %0, %1;" : "=r"(r) : "f"(f));
    return r;
}

__global__ __launch_bounds__(256) void gemm_tf32(
    const float* __restrict__ A, const float* __restrict__ B,
    const float* __restrict__ bias, float* __restrict__ C,
    int M, int N, int K)
{
    __shared__ uint32_t As[128][33];   // [m][k]
    __shared__ uint32_t Bs[32][132];   // [k][n]

    const int tid  = threadIdx.x;
    const int lane = tid & 31;
    const int warp = tid >> 5;
    const int wm = (warp >> 2) * 64;   // warp M offset (0 or 64)
    const int wn = (warp & 3) * 32;    // warp N offset (0,32,64,96)
    const int rowBase = blockIdx.y * 128;
    const int colBase = blockIdx.x * 128;

    float acc[4][4][4];
#pragma unroll
    for (int i = 0; i < 4; i++)
#pragma unroll
        for (int j = 0; j < 4; j++)
#pragma unroll
            for (int r = 0; r < 4; r++) acc[i][j][r] = 0.f;

    const int arow = tid >> 3;          // 0..31 (A rows per pass)
    const int acol = (tid & 7) * 4;     // 0,4,...,28
    const int brow8 = tid >> 5;         // 0..7
    const int bcol = (tid & 31) * 4;    // 0..124

    for (int k0 = 0; k0 < K; k0 += 32) {
        // Load A tile: 128 rows x 32 cols, 4 passes of 32 rows
#pragma unroll
        for (int p = 0; p < 4; p++) {
            int r = arow + p * 32;
            int gr = rowBase + r;
            float4 v = make_float4(0.f, 0.f, 0.f, 0.f);
            if (gr < M)
                v = *(const float4*)&A[(size_t)gr * K + k0 + acol];
            As[r][acol + 0] = f2tf32(v.x);
            As[r][acol + 1] = f2tf32(v.y);
            As[r][acol + 2] = f2tf32(v.z);
            As[r][acol + 3] = f2tf32(v.w);
        }
        // Load B tile: 32 rows x 128 cols, 4 passes of 8 rows
#pragma unroll
        for (int p = 0; p < 4; p++) {
            int r = brow8 + p * 8;
            int gc = colBase + bcol;
            float4 v = make_float4(0.f, 0.f, 0.f, 0.f);
            if (gc < N)
                v = *(const float4*)&B[(size_t)(k0 + r) * N + gc];
            Bs[r][bcol + 0] = f2tf32(v.x);
            Bs[r][bcol + 1] = f2tf32(v.y);
            Bs[r][bcol + 2] = f2tf32(v.z);
            Bs[r][bcol + 3] = f2tf32(v.w);
        }
        __syncthreads();

#pragma unroll
        for (int kk = 0; kk < 32; kk += 8) {
            uint32_t af[4][4];
#pragma unroll
            for (int mt = 0; mt < 4; mt++) {
                int r0 = wm + mt * 16 + (lane >> 2);
                int kc = kk + (lane & 3);
                af[mt][0] = As[r0][kc];
                af[mt][1] = As[r0 + 8][kc];
                af[mt][2] = As[r0][kc + 4];
                af[mt][3] = As[r0 + 8][kc + 4];
            }
            uint32_t bf[4][2];
#pragma unroll
            for (int nt = 0; nt < 4; nt++) {
                int c = wn + nt * 8 + (lane >> 2);
                int kc = kk + (lane & 3);
                bf[nt][0] = Bs[kc][c];
                bf[nt][1] = Bs[kc + 4][c];
            }
#pragma unroll
            for (int mt = 0; mt < 4; mt++)
#pragma unroll
                for (int nt = 0; nt < 4; nt++) {
                    asm volatile(
                        "mma.sync.aligned.m16n8k8.row.col.f32.tf32.tf32.f32 "
                        "{%0,%1,%2,%3}, {%4,%5,%6,%7}, {%8,%9}, {%0,%1,%2,%3};\n"
                        : "+f"(acc[mt][nt][0]), "+f"(acc[mt][nt][1]),
                          "+f"(acc[mt][nt][2]), "+f"(acc[mt][nt][3])
                        : "r"(af[mt][0]), "r"(af[mt][1]),
                          "r"(af[mt][2]), "r"(af[mt][3]),
                          "r"(bf[nt][0]), "r"(bf[nt][1]));
                }
        }
        __syncthreads();
    }

    // Epilogue: bias + store (guarded)
#pragma unroll
    for (int mt = 0; mt < 4; mt++) {
        int row0 = rowBase + wm + mt * 16 + (lane >> 2);
        int row1 = row0 + 8;
#pragma unroll
        for (int nt = 0; nt < 4; nt++) {
            int col = colBase + wn + nt * 8 + (lane & 3) * 2;
            if (col < N) {
                float b0 = bias[col];
                float b1 = bias[col + 1];
                if (row0 < M) {
                    C[(size_t)row0 * N + col]     = acc[mt][nt][0] + b0;
                    C[(size_t)row0 * N + col + 1] = acc[mt][nt][1] + b1;
                }
                if (row1 < M) {
                    C[(size_t)row1 * N + col]     = acc[mt][nt][2] + b0;
                    C[(size_t)row1 * N + col + 1] = acc[mt][nt][3] + b1;
                }
            }
        }
    }
}

// ---------------------------------------------------------------------------
// Softmax (per head over 12 entries) + sampling-location math.
// One thread per (fq, h): 38400 threads.
// ---------------------------------------------------------------------------
__global__ __launch_bounds__(256) void loc_kernel(const float* __restrict__ refp)
{
    int gid = blockIdx.x * blockDim.x + threadIdx.x;
    if (gid >= NQ * NH) return;
    int fq = gid >> 3;
    int h  = gid & 7;

    const float* a = &g_attn[(size_t)fq * TPX + h * 12];
    float e[12];
    float m = a[0];
#pragma unroll
    for (int r = 1; r < 12; r++) m = fmaxf(m, a[r]);
    float s = 0.f;
#pragma unroll
    for (int r = 0; r < 12; r++) { e[r] = __expf(a[r] - m); s += e[r]; }
    float inv = 1.f / s;

    const float* offp = &g_off[(size_t)fq * 192 + h * 24];
#pragma unroll
    for (int r = 0; r < 12; r++) {
        int l = r >> 2;
        float4 rp = *(const float4*)&refp[((size_t)fq * NL + l) * 4];
        float ox = offp[r * 2 + 0];
        float oy = offp[r * 2 + 1];
        float lx = rp.x + ox * 0.125f * rp.z;
        float ly = rp.y + oy * 0.125f * rp.w;
        float4 o;
        o.x = lx * (float)c_w[l] - 0.5f;
        o.y = ly * (float)c_h[l] - 0.5f;
        o.z = e[r] * inv;
        o.w = 0.f;
        g_samp[(size_t)fq * TPX + h * 12 + r] = o;
    }
}

// ---------------------------------------------------------------------------
// Deformable sampling + aggregation. One warp per (n,q,h).
// 32 lanes = 32 head channels. 12 points x 4 bilinear corners.
// ---------------------------------------------------------------------------
__global__ __launch_bounds__(256) void sample_kernel()
{
    const int warpInBlock = threadIdx.x >> 5;
    const int lane = threadIdx.x & 31;
    const int wg = blockIdx.x * 8 + warpInBlock;   // 0 .. 38399
    const int h  = wg & 7;
    const int fq = wg >> 3;                        // flat (n*300+q)
    const int n  = fq / LQ;

    float4 s = make_float4(0.f, 0.f, 0.f, 0.f);
    if (lane < 12) s = g_samp[(size_t)fq * TPX + h * 12 + lane];

    const float* vbase = &g_v[((size_t)n * LV) * CC + h * HD + lane];

    float acc = 0.f;
#pragma unroll
    for (int r = 0; r < 12; r++) {
        float gx = __shfl_sync(0xffffffffu, s.x, r);
        float gy = __shfl_sync(0xffffffffu, s.y, r);
        float aw = __shfl_sync(0xffffffffu, s.z, r);
        int l = r >> 2;
        int W = c_w[l], Hh = c_h[l], st = c_start[l];

        float x0f = floorf(gx), y0f = floorf(gy);
        float fx = gx - x0f, fy = gy - y0f;
        int ix = (int)x0f, iy = (int)y0f;

        bool vx0 = (ix >= 0) & (ix < W);
        bool vx1 = (ix + 1 >= 0) & (ix + 1 < W);
        bool vy0 = (iy >= 0) & (iy < Hh);
        bool vy1 = (iy + 1 >= 0) & (iy + 1 < Hh);

        const float* row0 = vbase + (size_t)(st + iy * W) * CC;
        const float* row1 = row0 + (size_t)W * CC;

        float v00 = (vx0 & vy0) ? row0[(size_t)ix * CC]       : 0.f;
        float v01 = (vx1 & vy0) ? row0[(size_t)(ix + 1) * CC] : 0.f;
        float v10 = (vx0 & vy1) ? row1[(size_t)ix * CC]       : 0.f;
        float v11 = (vx1 & vy1) ? row1[(size_t)(ix + 1) * CC] : 0.f;

        float bil = v00 * (1.f - fx) * (1.f - fy)
                  + v01 * fx * (1.f - fy)
                  + v10 * (1.f - fx) * fy
                  + v11 * fx * fy;
        acc += aw * bil;
    }
    g_mid[(size_t)fq * CC + h * HD + lane] = acc;
}

// ---------------------------------------------------------------------------
extern "C" void kernel_launch(void* const* d_in, const int* in_sizes, int n_in,
                              void* d_out, int out_size)
{
    const float* query = (const float*)d_in[0];
    const float* refp  = (const float*)d_in[1];
    const float* value = (const float*)d_in[2];
    const float* Woff  = (const float*)d_in[3];
    const float* boff  = (const float*)d_in[4];
    const float* Wattn = (const float*)d_in[5];
    const float* battn = (const float*)d_in[6];
    const float* Wval  = (const float*)d_in[7];
    const float* bval  = (const float*)d_in[8];
    const float* Wout  = (const float*)d_in[9];
    const float* bout  = (const float*)d_in[10];
    float* out = (float*)d_out;

    float *d_v, *d_off, *d_attn, *d_mid;
    cudaGetSymbolAddress((void**)&d_v,   g_v);
    cudaGetSymbolAddress((void**)&d_off, g_off);
    cudaGetSymbolAddress((void**)&d_attn,g_attn);
    cudaGetSymbolAddress((void**)&d_mid, g_mid);

    // 1) v = value @ W_val + b_val  (M=134400, N=256, K=256)
    gemm_tf32<<<dim3(2, (NB * LV) / 128), 256>>>(value, Wval, bval, d_v,
                                                 NB * LV, CC, CC);
    // 2) off = query @ W_off + b_off  (M=4800, N=192)
    gemm_tf32<<<dim3(2, (NQ + 127) / 128), 256>>>(query, Woff, boff, d_off,
                                                  NQ, 192, CC);
    // 3) attn = query @ W_attn + b_attn  (M=4800, N=96)
    gemm_tf32<<<dim3(1, (NQ + 127) / 128), 256>>>(query, Wattn, battn, d_attn,
                                                  NQ, TPX, CC);
    // 4) softmax + sampling locations
    loc_kernel<<<(NQ * NH + 255) / 256, 256>>>(refp);
    // 5) deformable sampling/aggregation
    sample_kernel<<<(NQ * NH) / 8, 256>>>();
    // 6) out = mid @ W_out + b_out  (M=4800, N=256)
    gemm_tf32<<<dim3(2, (NQ + 127) / 128), 256>>>(d_mid, Wout, bout, out,
                                                  NQ, CC, CC);
}

// round 8
// speedup vs baseline: 2.1680x; 1.4662x over previous
#include <cuda_runtime.h>
#include <cuda_bf16.h>
#include <math.h>
#include <stdint.h>

// Problem constants
#define NB 16          // batch
#define LQ 300         // queries
#define CC 256         // channels
#define NH 8           // heads
#define HD 32          // head dim
#define NL 3           // levels
#define NP 4           // points
#define LV 8400        // total spatial positions
#define TPX 96         // H*L*P
#define NQ (NB * LQ)   // 4800 flat queries

// Scratch (device globals; no runtime allocation allowed)
__device__ float  g_v[NB * LV * CC];          // value @ W_val + b_val   (137.6 MB)
__device__ float  g_off[NQ * 192];            // offset GEMM out         (3.7 MB)
__device__ float  g_attn[NQ * TPX];           // attn GEMM out (pre-softmax)
__device__ float  g_mid[NQ * CC];             // per-head aggregated     (4.9 MB)

__constant__ int c_start[NL] = {0, 6400, 8000};
__constant__ int c_w[NL]     = {80, 40, 20};
__constant__ int c_h[NL]     = {80, 40, 20};

// ---------------------------------------------------------------------------
// TF32 tensor-core GEMM: C = A(MxK) @ B(KxN) + bias
// BM=128, BN=128, BK=32. 256 threads = 8 warps (2 M x 4 N), warp tile 64x32.
// Software-pipelined: next k-tile staged in registers during MMA phase.
// A smem padded to 36 (36 mod 32 == 4) -> conflict-free A-fragment LDS.
// K must be a multiple of 32; M, N arbitrary (guarded), N % 4 == 0.
// ---------------------------------------------------------------------------
__device__ __forceinline__ uint32_t f2tf32(float f) {
    uint32_t r;
    asm("cvt.rna.tf32.f32 %0, %1;" : "=r"(r) : "f"(f));
    return r;
}

__global__ __launch_bounds__(256) void gemm_tf32(
    const float* __restrict__ A, const float* __restrict__ B,
    const float* __restrict__ bias, float* __restrict__ C,
    int M, int N, int K)
{
    __shared__ uint32_t As[128][36];   // [m][k], pad 36 -> bank = (4r+k)%32, bijective
    __shared__ uint32_t Bs[32][132];   // [k][n], pad 132 -> max 2-way on frag loads

    const int tid  = threadIdx.x;
    const int lane = tid & 31;
    const int warp = tid >> 5;
    const int wm = (warp >> 2) * 64;   // warp M offset (0 or 64)
    const int wn = (warp & 3) * 32;    // warp N offset (0,32,64,96)
    const int rowBase = blockIdx.y * 128;
    const int colBase = blockIdx.x * 128;

    float acc[4][4][4];
#pragma unroll
    for (int i = 0; i < 4; i++)
#pragma unroll
        for (int j = 0; j < 4; j++)
#pragma unroll
            for (int r = 0; r < 4; r++) acc[i][j][r] = 0.f;

    const int arow = tid >> 3;          // 0..31 (A rows per pass)
    const int acol = (tid & 7) * 4;     // 0,4,...,28
    const int brow8 = tid >> 5;         // 0..7
    const int bcol = (tid & 31) * 4;    // 0..124

    float4 stA[4], stB[4];

    // Prologue: stage k-tile 0 into registers
#pragma unroll
    for (int p = 0; p < 4; p++) {
        int gr = rowBase + arow + p * 32;
        stA[p] = (gr < M) ? *(const float4*)&A[(size_t)gr * K + acol]
                          : make_float4(0.f, 0.f, 0.f, 0.f);
    }
#pragma unroll
    for (int p = 0; p < 4; p++) {
        int gc = colBase + bcol;
        stB[p] = (gc < N) ? *(const float4*)&B[(size_t)(brow8 + p * 8) * N + gc]
                          : make_float4(0.f, 0.f, 0.f, 0.f);
    }

    for (int k0 = 0; k0 < K; k0 += 32) {
        // Commit staged registers to smem (rna conversion happens once here)
#pragma unroll
        for (int p = 0; p < 4; p++) {
            int r = arow + p * 32;
            As[r][acol + 0] = f2tf32(stA[p].x);
            As[r][acol + 1] = f2tf32(stA[p].y);
            As[r][acol + 2] = f2tf32(stA[p].z);
            As[r][acol + 3] = f2tf32(stA[p].w);
        }
#pragma unroll
        for (int p = 0; p < 4; p++) {
            int r = brow8 + p * 8;
            Bs[r][bcol + 0] = f2tf32(stB[p].x);
            Bs[r][bcol + 1] = f2tf32(stB[p].y);
            Bs[r][bcol + 2] = f2tf32(stB[p].z);
            Bs[r][bcol + 3] = f2tf32(stB[p].w);
        }
        __syncthreads();

        // Prefetch next k-tile into registers (overlaps with MMA phase below)
        int kn = k0 + 32;
        if (kn < K) {
#pragma unroll
            for (int p = 0; p < 4; p++) {
                int gr = rowBase + arow + p * 32;
                stA[p] = (gr < M) ? *(const float4*)&A[(size_t)gr * K + kn + acol]
                                  : make_float4(0.f, 0.f, 0.f, 0.f);
            }
#pragma unroll
            for (int p = 0; p < 4; p++) {
                int gc = colBase + bcol;
                stB[p] = (gc < N) ? *(const float4*)&B[(size_t)(kn + brow8 + p * 8) * N + gc]
                                  : make_float4(0.f, 0.f, 0.f, 0.f);
            }
        }

        // MMA phase
#pragma unroll
        for (int kk = 0; kk < 32; kk += 8) {
            uint32_t af[4][4];
#pragma unroll
            for (int mt = 0; mt < 4; mt++) {
                int r0 = wm + mt * 16 + (lane >> 2);
                int kc = kk + (lane & 3);
                af[mt][0] = As[r0][kc];
                af[mt][1] = As[r0 + 8][kc];
                af[mt][2] = As[r0][kc + 4];
                af[mt][3] = As[r0 + 8][kc + 4];
            }
            uint32_t bf[4][2];
#pragma unroll
            for (int nt = 0; nt < 4; nt++) {
                int c = wn + nt * 8 + (lane >> 2);
                int kc = kk + (lane & 3);
                bf[nt][0] = Bs[kc][c];
                bf[nt][1] = Bs[kc + 4][c];
            }
#pragma unroll
            for (int mt = 0; mt < 4; mt++)
#pragma unroll
                for (int nt = 0; nt < 4; nt++) {
                    asm volatile(
                        "mma.sync.aligned.m16n8k8.row.col.f32.tf32.tf32.f32 "
                        "{%0,%1,%2,%3}, {%4,%5,%6,%7}, {%8,%9}, {%0,%1,%2,%3};\n"
                        : "+f"(acc[mt][nt][0]), "+f"(acc[mt][nt][1]),
                          "+f"(acc[mt][nt][2]), "+f"(acc[mt][nt][3])
                        : "r"(af[mt][0]), "r"(af[mt][1]),
                          "r"(af[mt][2]), "r"(af[mt][3]),
                          "r"(bf[nt][0]), "r"(bf[nt][1]));
                }
        }
        __syncthreads();
    }

    // Epilogue: bias + store (guarded)
#pragma unroll
    for (int mt = 0; mt < 4; mt++) {
        int row0 = rowBase + wm + mt * 16 + (lane >> 2);
        int row1 = row0 + 8;
#pragma unroll
        for (int nt = 0; nt < 4; nt++) {
            int col = colBase + wn + nt * 8 + (lane & 3) * 2;
            if (col < N) {
                float b0 = bias[col];
                float b1 = bias[col + 1];
                if (row0 < M) {
                    C[(size_t)row0 * N + col]     = acc[mt][nt][0] + b0;
                    C[(size_t)row0 * N + col + 1] = acc[mt][nt][1] + b1;
                }
                if (row1 < M) {
                    C[(size_t)row1 * N + col]     = acc[mt][nt][2] + b0;
                    C[(size_t)row1 * N + col + 1] = acc[mt][nt][3] + b1;
                }
            }
        }
    }
}

// ---------------------------------------------------------------------------
// Fused softmax + sampling-location + deformable sampling/aggregation.
// One warp per (n,q,h). Lanes 0..11 own one (l,p) point each: warp-shfl
// softmax over the 12 attention logits, then per-point pixel coords.
// Then all 32 lanes = 32 head channels do the bilinear gathers.
// ---------------------------------------------------------------------------
__global__ __launch_bounds__(256) void sample_kernel(const float* __restrict__ refp)
{
    const int warpInBlock = threadIdx.x >> 5;
    const int lane = threadIdx.x & 31;
    const int wg = blockIdx.x * 8 + warpInBlock;   // 0 .. 38399
    const int h  = wg & 7;
    const int fq = wg >> 3;                        // flat (n*300+q)
    const int n  = fq / LQ;

    // --- softmax over 12 logits (lanes >= 12 contribute neutral values) ---
    float av = (lane < 12) ? g_attn[(size_t)fq * TPX + h * 12 + lane] : -3.4e38f;
    float m = av;
#pragma unroll
    for (int o = 16; o > 0; o >>= 1)
        m = fmaxf(m, __shfl_xor_sync(0xffffffffu, m, o));
    float e = (lane < 12) ? __expf(av - m) : 0.f;
    float ssum = e;
#pragma unroll
    for (int o = 16; o > 0; o >>= 1)
        ssum += __shfl_xor_sync(0xffffffffu, ssum, o);
    float inv = 1.f / ssum;
    float aw_l = e * inv;

    // --- sampling location for this lane's point ---
    float gx_l = 0.f, gy_l = 0.f;
    if (lane < 12) {
        int l = lane >> 2;
        float4 rp = *(const float4*)&refp[((size_t)fq * NL + l) * 4];
        float ox = g_off[(size_t)fq * 192 + h * 24 + lane * 2 + 0];
        float oy = g_off[(size_t)fq * 192 + h * 24 + lane * 2 + 1];
        float lx = rp.x + ox * 0.125f * rp.z;
        float ly = rp.y + oy * 0.125f * rp.w;
        gx_l = lx * (float)c_w[l] - 0.5f;
        gy_l = ly * (float)c_h[l] - 0.5f;
    }

    // --- bilinear sampling: 32 lanes = 32 head channels ---
    const float* vbase = &g_v[((size_t)n * LV) * CC + h * HD + lane];

    float acc = 0.f;
#pragma unroll
    for (int r = 0; r < 12; r++) {
        float gx = __shfl_sync(0xffffffffu, gx_l, r);
        float gy = __shfl_sync(0xffffffffu, gy_l, r);
        float aw = __shfl_sync(0xffffffffu, aw_l, r);
        int l = r >> 2;
        int W = c_w[l], Hh = c_h[l], st = c_start[l];

        float x0f = floorf(gx), y0f = floorf(gy);
        float fx = gx - x0f, fy = gy - y0f;
        int ix = (int)x0f, iy = (int)y0f;

        bool vx0 = (ix >= 0) & (ix < W);
        bool vx1 = (ix + 1 >= 0) & (ix + 1 < W);
        bool vy0 = (iy >= 0) & (iy < Hh);
        bool vy1 = (iy + 1 >= 0) & (iy + 1 < Hh);

        const float* row0 = vbase + (size_t)(st + iy * W) * CC;
        const float* row1 = row0 + (size_t)W * CC;

        float v00 = (vx0 & vy0) ? row0[(size_t)ix * CC]       : 0.f;
        float v01 = (vx1 & vy0) ? row0[(size_t)(ix + 1) * CC] : 0.f;
        float v10 = (vx0 & vy1) ? row1[(size_t)ix * CC]       : 0.f;
        float v11 = (vx1 & vy1) ? row1[(size_t)(ix + 1) * CC] : 0.f;

        float bil = v00 * (1.f - fx) * (1.f - fy)
                  + v01 * fx * (1.f - fy)
                  + v10 * (1.f - fx) * fy
                  + v11 * fx * fy;
        acc += aw * bil;
    }
    g_mid[(size_t)fq * CC + h * HD + lane] = acc;
}

// ---------------------------------------------------------------------------
extern "C" void kernel_launch(void* const* d_in, const int* in_sizes, int n_in,
                              void* d_out, int out_size)
{
    const float* query = (const float*)d_in[0];
    const float* refp  = (const float*)d_in[1];
    const float* value = (const float*)d_in[2];
    const float* Woff  = (const float*)d_in[3];
    const float* boff  = (const float*)d_in[4];
    const float* Wattn = (const float*)d_in[5];
    const float* battn = (const float*)d_in[6];
    const float* Wval  = (const float*)d_in[7];
    const float* bval  = (const float*)d_in[8];
    const float* Wout  = (const float*)d_in[9];
    const float* bout  = (const float*)d_in[10];
    float* out = (float*)d_out;

    float *d_v, *d_off, *d_attn, *d_mid;
    cudaGetSymbolAddress((void**)&d_v,   g_v);
    cudaGetSymbolAddress((void**)&d_off, g_off);
    cudaGetSymbolAddress((void**)&d_attn,g_attn);
    cudaGetSymbolAddress((void**)&d_mid, g_mid);

    // 1) v = value @ W_val + b_val  (M=134400, N=256, K=256)
    gemm_tf32<<<dim3(2, (NB * LV) / 128), 256>>>(value, Wval, bval, d_v,
                                                 NB * LV, CC, CC);
    // 2) off = query @ W_off + b_off  (M=4800, N=192)
    gemm_tf32<<<dim3(2, (NQ + 127) / 128), 256>>>(query, Woff, boff, d_off,
                                                  NQ, 192, CC);
    // 3) attn = query @ W_attn + b_attn  (M=4800, N=96)
    gemm_tf32<<<dim3(1, (NQ + 127) / 128), 256>>>(query, Wattn, battn, d_attn,
                                                  NQ, TPX, CC);
    // 4) fused softmax + locations + deformable sampling/aggregation
    sample_kernel<<<(NQ * NH) / 8, 256>>>(refp);
    // 5) out = mid @ W_out + b_out  (M=4800, N=256)
    gemm_tf32<<<dim3(2, (NQ + 127) / 128), 256>>>(d_mid, Wout, bout, out,
                                                  NQ, CC, CC);
}